// round 6
// baseline (speedup 1.0000x reference)
#include <cuda_runtime.h>

#define WARPS_PER_BLOCK 8
#define THREADS_PER_BLOCK (WARPS_PER_BLOCK * 32)
#define BLOCKS_PER_SM 8
#define NUM_BLOCKS (152 * BLOCKS_PER_SM)   // persistent: one exact wave
#define GRAB 64                            // atoms per work-steal grab (mult of 4)

__device__ unsigned int g_work_counter;

__global__ void zero_out_kernel(float* out, int n) {
    int i = blockIdx.x * blockDim.x + threadIdx.x;
    if (i < n) out[i] = 0.0f;
    if (i == 0) g_work_counter = 0u;   // reset per launch (graph-replay safe)
}

// Warp-reduce per-lane accumulator and atomically flush to out[seg_id].
__device__ __forceinline__ void flush_seg(float& acc, int seg_id, int lane,
                                          float* __restrict__ out) {
    float s = acc;
    #pragma unroll
    for (int off = 16; off > 0; off >>= 1)
        s += __shfl_xor_sync(0xFFFFFFFFu, s, off);
    if (lane == 0) atomicAdd(&out[seg_id], s);
    acc = 0.0f;
}

__launch_bounds__(THREADS_PER_BLOCK, BLOCKS_PER_SM)
__global__ void atomwise_readout_kernel(const float4* __restrict__ f4,
                                        const int* __restrict__ seg,
                                        const float* __restrict__ w,
                                        float* __restrict__ out,
                                        int n_atoms) {
    const int lane = threadIdx.x & 31;
    const float4 wv = reinterpret_cast<const float4*>(w)[lane];  // L1/L2 hit

    while (true) {
        // One lane grabs the next chunk; broadcast to the warp.
        unsigned int grab_idx;
        if (lane == 0) grab_idx = atomicAdd(&g_work_counter, 1u);
        grab_idx = __shfl_sync(0xFFFFFFFFu, grab_idx, 0);

        long long start = (long long)grab_idx * GRAB;
        if (start >= n_atoms) break;
        long long end = start + GRAB;
        if (end > n_atoms) end = n_atoms;

        int   cur_seg = seg[start];
        float acc     = 0.0f;   // per-LANE partial for current segment run

        long long a = start;
        const float4* p = f4 + start * 32 + lane;

        // 4 atoms/iter; start is GRAB-aligned (mult of 4) -> int4 seg loads OK
        for (; a + 4 <= end; a += 4, p += 128) {
            int4 g = *reinterpret_cast<const int4*>(&seg[a]);

            float4 v0 = __ldcs(p);
            float4 v1 = __ldcs(p + 32);
            float4 v2 = __ldcs(p + 64);
            float4 v3 = __ldcs(p + 96);

            float s0 = fmaf(v0.x, wv.x, fmaf(v0.y, wv.y, fmaf(v0.z, wv.z, v0.w * wv.w)));
            float s1 = fmaf(v1.x, wv.x, fmaf(v1.y, wv.y, fmaf(v1.z, wv.z, v1.w * wv.w)));
            float s2 = fmaf(v2.x, wv.x, fmaf(v2.y, wv.y, fmaf(v2.z, wv.z, v2.w * wv.w)));
            float s3 = fmaf(v3.x, wv.x, fmaf(v3.y, wv.y, fmaf(v3.z, wv.z, v3.w * wv.w)));

            if (g.w == cur_seg) {
                acc += (s0 + s1) + (s2 + s3);   // fast path: quad in one segment
            } else {
                if (g.x != cur_seg) { flush_seg(acc, cur_seg, lane, out); cur_seg = g.x; }
                acc += s0;
                if (g.y != cur_seg) { flush_seg(acc, cur_seg, lane, out); cur_seg = g.y; }
                acc += s1;
                if (g.z != cur_seg) { flush_seg(acc, cur_seg, lane, out); cur_seg = g.z; }
                acc += s2;
                if (g.w != cur_seg) { flush_seg(acc, cur_seg, lane, out); cur_seg = g.w; }
                acc += s3;
            }
        }

        // Tail (< 4 atoms, only at the very end of the array)
        for (; a < end; a++, p += 32) {
            float4 v = __ldcs(p);
            float s = fmaf(v.x, wv.x, fmaf(v.y, wv.y, fmaf(v.z, wv.z, v.w * wv.w)));
            int gg = seg[a];
            if (gg != cur_seg) { flush_seg(acc, cur_seg, lane, out); cur_seg = gg; }
            acc += s;
        }

        flush_seg(acc, cur_seg, lane, out);
    }
}

extern "C" void kernel_launch(void* const* d_in, const int* in_sizes, int n_in,
                              void* d_out, int out_size) {
    const float* f   = (const float*)d_in[0];
    const int*   seg = (const int*)d_in[1];
    const float* w   = (const float*)d_in[n_in - 1];  // w_e (128 floats) is last

    const int n_atoms = in_sizes[1];
    float* out = (float*)d_out;

    {
        int threads = 256;
        int blocks  = (out_size + threads - 1) / threads;
        zero_out_kernel<<<blocks, threads>>>(out, out_size);
    }

    atomwise_readout_kernel<<<NUM_BLOCKS, THREADS_PER_BLOCK>>>(
        reinterpret_cast<const float4*>(f), seg, w, out, n_atoms);
}

// round 7
// speedup vs baseline: 1.0987x; 1.0987x over previous
#include <cuda_runtime.h>

#define WARPS_PER_BLOCK 8
#define THREADS_PER_BLOCK (WARPS_PER_BLOCK * 32)
#define BLOCKS_PER_SM 8
#define NUM_WAVES 8
#define NUM_BLOCKS (152 * BLOCKS_PER_SM * NUM_WAVES)  // static oversubscription:
                                                      // CLC streams blocks onto
                                                      // free SMs -> self-balancing

__global__ void zero_out_kernel(float* out, int n) {
    int i = blockIdx.x * blockDim.x + threadIdx.x;
    if (i < n) out[i] = 0.0f;
}

// Warp-reduce per-lane accumulator and atomically flush to out[seg_id].
__device__ __forceinline__ void flush_seg(float& acc, int seg_id, int lane,
                                          float* __restrict__ out) {
    float s = acc;
    #pragma unroll
    for (int off = 16; off > 0; off >>= 1)
        s += __shfl_xor_sync(0xFFFFFFFFu, s, off);
    if (lane == 0) atomicAdd(&out[seg_id], s);
    acc = 0.0f;
}

__launch_bounds__(THREADS_PER_BLOCK, BLOCKS_PER_SM)
__global__ void atomwise_readout_kernel(const float4* __restrict__ f4,
                                        const int* __restrict__ seg,
                                        const float* __restrict__ w,
                                        float* __restrict__ out,
                                        int n_atoms, int chunk) {
    const int lane = threadIdx.x & 31;
    const int warp_global = blockIdx.x * WARPS_PER_BLOCK + (threadIdx.x >> 5);

    long long start = (long long)warp_global * chunk;   // chunk is 4-aligned
    if (start >= n_atoms) return;
    long long end = start + chunk;
    if (end > n_atoms) end = n_atoms;

    const float4 wv = reinterpret_cast<const float4*>(w)[lane];  // L1/L2 hit

    int   cur_seg = seg[start];
    float acc     = 0.0f;     // per-LANE partial sum for current segment run

    long long a = start;
    const float4* p = f4 + start * 32 + lane;

    // Main loop: 4 atoms/iter. 5 loads batched at the top; sorted seg ids ->
    // per-lane accumulation, warp-reduce only on segment change.
    for (; a + 4 <= end; a += 4, p += 128) {
        int4 g = *reinterpret_cast<const int4*>(&seg[a]);

        float4 v0 = __ldcs(p);
        float4 v1 = __ldcs(p + 32);
        float4 v2 = __ldcs(p + 64);
        float4 v3 = __ldcs(p + 96);

        float s0 = fmaf(v0.x, wv.x, fmaf(v0.y, wv.y, fmaf(v0.z, wv.z, v0.w * wv.w)));
        float s1 = fmaf(v1.x, wv.x, fmaf(v1.y, wv.y, fmaf(v1.z, wv.z, v1.w * wv.w)));
        float s2 = fmaf(v2.x, wv.x, fmaf(v2.y, wv.y, fmaf(v2.z, wv.z, v2.w * wv.w)));
        float s3 = fmaf(v3.x, wv.x, fmaf(v3.y, wv.y, fmaf(v3.z, wv.z, v3.w * wv.w)));

        if (g.w == cur_seg) {
            acc += (s0 + s1) + (s2 + s3);   // fast path: quad in one segment
        } else {
            if (g.x != cur_seg) { flush_seg(acc, cur_seg, lane, out); cur_seg = g.x; }
            acc += s0;
            if (g.y != cur_seg) { flush_seg(acc, cur_seg, lane, out); cur_seg = g.y; }
            acc += s1;
            if (g.z != cur_seg) { flush_seg(acc, cur_seg, lane, out); cur_seg = g.z; }
            acc += s2;
            if (g.w != cur_seg) { flush_seg(acc, cur_seg, lane, out); cur_seg = g.w; }
            acc += s3;
        }
    }

    // Tail (< 4 atoms)
    for (; a < end; a++, p += 32) {
        float4 v = __ldcs(p);
        float s = fmaf(v.x, wv.x, fmaf(v.y, wv.y, fmaf(v.z, wv.z, v.w * wv.w)));
        int gg = seg[a];
        if (gg != cur_seg) { flush_seg(acc, cur_seg, lane, out); cur_seg = gg; }
        acc += s;
    }

    flush_seg(acc, cur_seg, lane, out);
}

extern "C" void kernel_launch(void* const* d_in, const int* in_sizes, int n_in,
                              void* d_out, int out_size) {
    const float* f   = (const float*)d_in[0];
    const int*   seg = (const int*)d_in[1];
    const float* w   = (const float*)d_in[n_in - 1];  // w_e (128 floats) is last

    const int n_atoms = in_sizes[1];
    float* out = (float*)d_out;

    {
        int threads = 128;
        int blocks  = (out_size + threads - 1) / threads;
        zero_out_kernel<<<blocks, threads>>>(out, out_size);
    }

    const long long total_warps = (long long)NUM_BLOCKS * WARPS_PER_BLOCK;
    int chunk = (int)((n_atoms + total_warps - 1) / total_warps);
    chunk = (chunk + 3) & ~3;   // 4-aligned so int4 seg loads are aligned

    atomwise_readout_kernel<<<NUM_BLOCKS, THREADS_PER_BLOCK>>>(
        reinterpret_cast<const float4*>(f), seg, w, out, n_atoms, chunk);
}

// round 8
// speedup vs baseline: 1.1134x; 1.0134x over previous
#include <cuda_runtime.h>

#define WARPS_PER_BLOCK 8
#define THREADS_PER_BLOCK (WARPS_PER_BLOCK * 32)
#define BLOCKS_PER_SM 8
#define CHUNK 16   // atoms per warp (multiple of 4); grid sized to cover exactly

__global__ void zero_out_kernel(float* out, int n) {
    int i = blockIdx.x * blockDim.x + threadIdx.x;
    if (i < n) out[i] = 0.0f;
}

// Warp-reduce per-lane accumulator and atomically flush to out[seg_id].
__device__ __forceinline__ void flush_seg(float& acc, int seg_id, int lane,
                                          float* __restrict__ out) {
    float s = acc;
    #pragma unroll
    for (int off = 16; off > 0; off >>= 1)
        s += __shfl_xor_sync(0xFFFFFFFFu, s, off);
    if (lane == 0) atomicAdd(&out[seg_id], s);
    acc = 0.0f;
}

__launch_bounds__(THREADS_PER_BLOCK, BLOCKS_PER_SM)
__global__ void atomwise_readout_kernel(const float4* __restrict__ f4,
                                        const int* __restrict__ seg,
                                        const float* __restrict__ w,
                                        float* __restrict__ out,
                                        int n_atoms) {
    const int lane = threadIdx.x & 31;
    const int warp_global = blockIdx.x * WARPS_PER_BLOCK + (threadIdx.x >> 5);

    long long start = (long long)warp_global * CHUNK;
    if (start >= n_atoms) return;
    long long end = start + CHUNK;
    if (end > n_atoms) end = n_atoms;

    const float4 wv = reinterpret_cast<const float4*>(w)[lane];  // L1/L2 hit

    int   cur_seg = seg[start];
    float acc     = 0.0f;     // per-LANE partial sum for current segment run

    long long a = start;
    const float4* p = f4 + start * 32 + lane;

    // Main loop: 4 atoms/iter. 5 loads batched at the top; sorted seg ids ->
    // per-lane accumulation, warp-reduce only on segment change.
    for (; a + 4 <= end; a += 4, p += 128) {
        int4 g = *reinterpret_cast<const int4*>(&seg[a]);

        float4 v0 = __ldcs(p);
        float4 v1 = __ldcs(p + 32);
        float4 v2 = __ldcs(p + 64);
        float4 v3 = __ldcs(p + 96);

        float s0 = fmaf(v0.x, wv.x, fmaf(v0.y, wv.y, fmaf(v0.z, wv.z, v0.w * wv.w)));
        float s1 = fmaf(v1.x, wv.x, fmaf(v1.y, wv.y, fmaf(v1.z, wv.z, v1.w * wv.w)));
        float s2 = fmaf(v2.x, wv.x, fmaf(v2.y, wv.y, fmaf(v2.z, wv.z, v2.w * wv.w)));
        float s3 = fmaf(v3.x, wv.x, fmaf(v3.y, wv.y, fmaf(v3.z, wv.z, v3.w * wv.w)));

        if (g.w == cur_seg) {
            acc += (s0 + s1) + (s2 + s3);   // fast path: quad in one segment
        } else {
            if (g.x != cur_seg) { flush_seg(acc, cur_seg, lane, out); cur_seg = g.x; }
            acc += s0;
            if (g.y != cur_seg) { flush_seg(acc, cur_seg, lane, out); cur_seg = g.y; }
            acc += s1;
            if (g.z != cur_seg) { flush_seg(acc, cur_seg, lane, out); cur_seg = g.z; }
            acc += s2;
            if (g.w != cur_seg) { flush_seg(acc, cur_seg, lane, out); cur_seg = g.w; }
            acc += s3;
        }
    }

    // Tail (< 4 atoms, only at the very end of the array)
    for (; a < end; a++, p += 32) {
        float4 v = __ldcs(p);
        float s = fmaf(v.x, wv.x, fmaf(v.y, wv.y, fmaf(v.z, wv.z, v.w * wv.w)));
        int gg = seg[a];
        if (gg != cur_seg) { flush_seg(acc, cur_seg, lane, out); cur_seg = gg; }
        acc += s;
    }

    flush_seg(acc, cur_seg, lane, out);
}

extern "C" void kernel_launch(void* const* d_in, const int* in_sizes, int n_in,
                              void* d_out, int out_size) {
    const float* f   = (const float*)d_in[0];
    const int*   seg = (const int*)d_in[1];
    const float* w   = (const float*)d_in[n_in - 1];  // w_e (128 floats) is last

    const int n_atoms = in_sizes[1];
    float* out = (float*)d_out;

    {
        int threads = 128;
        int blocks  = (out_size + threads - 1) / threads;
        zero_out_kernel<<<blocks, threads>>>(out, out_size);
    }

    // Exact cover: every warp (except possibly the last) gets exactly CHUNK atoms.
    const long long total_warps = ((long long)n_atoms + CHUNK - 1) / CHUNK;
    const int blocks = (int)((total_warps + WARPS_PER_BLOCK - 1) / WARPS_PER_BLOCK);

    atomwise_readout_kernel<<<blocks, THREADS_PER_BLOCK>>>(
        reinterpret_cast<const float4*>(f), seg, w, out, n_atoms);
}

// round 9
// speedup vs baseline: 1.1558x; 1.0380x over previous
#include <cuda_runtime.h>

#define WARPS_PER_BLOCK 8
#define THREADS_PER_BLOCK (WARPS_PER_BLOCK * 32)
#define BLOCKS_PER_SM 8
#define CHUNK 8   // atoms per warp (multiple of 4); grid sized to cover exactly

__global__ void zero_out_kernel(float* out, int n) {
    int i = blockIdx.x * blockDim.x + threadIdx.x;
    if (i < n) out[i] = 0.0f;
}

// Warp-reduce per-lane accumulator and atomically flush to out[seg_id].
__device__ __forceinline__ void flush_seg(float& acc, int seg_id, int lane,
                                          float* __restrict__ out) {
    float s = acc;
    #pragma unroll
    for (int off = 16; off > 0; off >>= 1)
        s += __shfl_xor_sync(0xFFFFFFFFu, s, off);
    if (lane == 0) atomicAdd(&out[seg_id], s);
    acc = 0.0f;
}

__launch_bounds__(THREADS_PER_BLOCK, BLOCKS_PER_SM)
__global__ void atomwise_readout_kernel(const float4* __restrict__ f4,
                                        const int* __restrict__ seg,
                                        const float* __restrict__ w,
                                        float* __restrict__ out,
                                        int n_atoms) {
    const int lane = threadIdx.x & 31;
    const int warp_global = blockIdx.x * WARPS_PER_BLOCK + (threadIdx.x >> 5);

    long long start = (long long)warp_global * CHUNK;
    if (start >= n_atoms) return;
    long long end = start + CHUNK;
    if (end > n_atoms) end = n_atoms;

    const float4 wv = reinterpret_cast<const float4*>(w)[lane];  // L1/L2 hit

    int   cur_seg = seg[start];
    float acc     = 0.0f;     // per-LANE partial sum for current segment run

    long long a = start;
    const float4* p = f4 + start * 32 + lane;

    // Main loop: 4 atoms/iter. 5 loads batched at the top; sorted seg ids ->
    // per-lane accumulation, warp-reduce only on segment change.
    for (; a + 4 <= end; a += 4, p += 128) {
        int4 g = *reinterpret_cast<const int4*>(&seg[a]);

        float4 v0 = __ldcs(p);
        float4 v1 = __ldcs(p + 32);
        float4 v2 = __ldcs(p + 64);
        float4 v3 = __ldcs(p + 96);

        float s0 = fmaf(v0.x, wv.x, fmaf(v0.y, wv.y, fmaf(v0.z, wv.z, v0.w * wv.w)));
        float s1 = fmaf(v1.x, wv.x, fmaf(v1.y, wv.y, fmaf(v1.z, wv.z, v1.w * wv.w)));
        float s2 = fmaf(v2.x, wv.x, fmaf(v2.y, wv.y, fmaf(v2.z, wv.z, v2.w * wv.w)));
        float s3 = fmaf(v3.x, wv.x, fmaf(v3.y, wv.y, fmaf(v3.z, wv.z, v3.w * wv.w)));

        if (g.w == cur_seg) {
            acc += (s0 + s1) + (s2 + s3);   // fast path: quad in one segment
        } else {
            if (g.x != cur_seg) { flush_seg(acc, cur_seg, lane, out); cur_seg = g.x; }
            acc += s0;
            if (g.y != cur_seg) { flush_seg(acc, cur_seg, lane, out); cur_seg = g.y; }
            acc += s1;
            if (g.z != cur_seg) { flush_seg(acc, cur_seg, lane, out); cur_seg = g.z; }
            acc += s2;
            if (g.w != cur_seg) { flush_seg(acc, cur_seg, lane, out); cur_seg = g.w; }
            acc += s3;
        }
    }

    // Tail (< 4 atoms, only at the very end of the array)
    for (; a < end; a++, p += 32) {
        float4 v = __ldcs(p);
        float s = fmaf(v.x, wv.x, fmaf(v.y, wv.y, fmaf(v.z, wv.z, v.w * wv.w)));
        int gg = seg[a];
        if (gg != cur_seg) { flush_seg(acc, cur_seg, lane, out); cur_seg = gg; }
        acc += s;
    }

    flush_seg(acc, cur_seg, lane, out);
}

extern "C" void kernel_launch(void* const* d_in, const int* in_sizes, int n_in,
                              void* d_out, int out_size) {
    const float* f   = (const float*)d_in[0];
    const int*   seg = (const int*)d_in[1];
    const float* w   = (const float*)d_in[n_in - 1];  // w_e (128 floats) is last

    const int n_atoms = in_sizes[1];
    float* out = (float*)d_out;

    {
        int threads = 128;
        int blocks  = (out_size + threads - 1) / threads;
        zero_out_kernel<<<blocks, threads>>>(out, out_size);
    }

    // Exact cover: every warp (except possibly the last) gets exactly CHUNK atoms.
    const long long total_warps = ((long long)n_atoms + CHUNK - 1) / CHUNK;
    const int blocks = (int)((total_warps + WARPS_PER_BLOCK - 1) / WARPS_PER_BLOCK);

    atomwise_readout_kernel<<<blocks, THREADS_PER_BLOCK>>>(
        reinterpret_cast<const float4*>(f), seg, w, out, n_atoms);
}